// round 16
// baseline (speedup 1.0000x reference)
#include <cuda_runtime.h>
#include <cuda_fp16.h>
#include <cstdint>

#define D 128
#define T 256
#define NTILES 1024          // 4 batches * 16 * 16 spatial tiles
#define NTHR 512
#define SCALE 0.08838834764831845f   // 128^-0.5

typedef unsigned long long ull;

// Packed fp16 M^T per axis: g_Mhf[axis][j][k] = (Wq^T Wk)[k,j] * SCALE
__device__ __half g_Mhf[2][D][D];

// ---- smem byte layout ----
// M/X: XOR-swizzled 256B rows (16B group g at row r lives at g^(r&7))
#define OFF_MW 0                 // fp16 M_w [128][128h] swizzled   32768 B
#define OFF_MH2 32768            // fp16 M_h [128][128h] swizzled   32768 B
#define OFF_X  65536             // fp16 X   [256][128h] swizzled   65536 B
#define OFF_KV 131072            // fp16 KV  [324 rows][136h pad]   88128 B
#define OFF_PTW 219200           // fp32 W partials [3][256][2]      6144 B
#define OFF_PTH 225344           // fp32 H partials [3][256][2]      6144 B
#define SMEM_TOTAL 231488

// ---------------------------------------------------------------------------
__device__ __forceinline__ uint32_t smem_u32(const void* p) {
    uint32_t a;
    asm("{ .reg .u64 t; cvta.to.shared.u64 t, %1; cvt.u32.u64 %0, t; }"
        : "=r"(a) : "l"(p));
    return a;
}
__device__ __forceinline__ void cpa16(uint32_t dst, const void* src) {
    asm volatile("cp.async.cg.shared.global [%0], [%1], 16;"
                 :: "r"(dst), "l"(src));
}
__device__ __forceinline__ void cpa_commit() {
    asm volatile("cp.async.commit_group;");
}
__device__ __forceinline__ void cpa_wait0() {
    asm volatile("cp.async.wait_group 0;" ::: "memory");
}
__device__ __forceinline__ void ldsm4(uint32_t* r, uint32_t a) {
    asm volatile("ldmatrix.sync.aligned.m8n8.x4.shared.b16 {%0,%1,%2,%3}, [%4];"
                 : "=r"(r[0]), "=r"(r[1]), "=r"(r[2]), "=r"(r[3]) : "r"(a));
}
__device__ __forceinline__ void mmah(float* d, const uint32_t* a,
                                     uint32_t b0, uint32_t b1) {
    asm volatile(
        "mma.sync.aligned.m16n8k16.row.col.f32.f16.f16.f32 "
        "{%0,%1,%2,%3},{%4,%5,%6,%7},{%8,%9},{%0,%1,%2,%3};"
        : "+f"(d[0]), "+f"(d[1]), "+f"(d[2]), "+f"(d[3])
        : "r"(a[0]), "r"(a[1]), "r"(a[2]), "r"(a[3]), "r"(b0), "r"(b1));
}
__device__ __forceinline__ ull pack4h(float4 v) {
    __half2 h0 = __floats2half2_rn(v.x, v.y);
    __half2 h1 = __floats2half2_rn(v.z, v.w);
    unsigned u0 = *(unsigned*)&h0, u1 = *(unsigned*)&h1;
    return (ull)u0 | ((ull)u1 << 32);
}
__device__ __forceinline__ uint32_t packh2(float a, float b) {
    __half2 h = __floats2half2_rn(a, b);
    return *(unsigned*)&h;
}

// ---------------------------------------------------------------------------
// Kernel 1: M^T[j][k] = sum_e Wq[e,k] * Wk[e,j] * SCALE  -> fp16 (per axis)
// ---------------------------------------------------------------------------
__global__ void compute_M_kernel(const float* __restrict__ Wq_h,
                                 const float* __restrict__ Wk_h,
                                 const float* __restrict__ Wq_w,
                                 const float* __restrict__ Wk_w) {
    int k = blockIdx.x, j = threadIdx.x, axis = blockIdx.y;
    const float* Wq = axis ? Wq_h : Wq_w;
    const float* Wk = axis ? Wk_h : Wk_w;
    __shared__ float sq[D];
    sq[j] = Wq[j * D + k];
    __syncthreads();
    float s = 0.f;
#pragma unroll 8
    for (int e = 0; e < D; e++) s = fmaf(sq[e], Wk[e * D + j], s);
    g_Mhf[axis][j][k] = __float2half(s * SCALE);
}

// ---------------------------------------------------------------------------
// Kernel 2: persistent fused both-axis axial attention, 16x16 tiles,
// 512 threads, both M resident, MMA dots decoupled via fp16 A-frag repack,
// deep KV prefetch into dead-acc registers, 3 barriers/tile.
// ---------------------------------------------------------------------------
__global__ __launch_bounds__(NTHR, 1)
void axial_fused(const float* __restrict__ x, const float* __restrict__ kv,
                 float* __restrict__ out) {
    extern __shared__ char sm[];
    const uint32_t sb = smem_u32(sm);
    const int tid = threadIdx.x, wid = tid >> 5, lane = tid & 31;
    const int rg = wid >> 1, cg = wid & 1;       // 8 row-groups x 2 col-groups
    const int qrow = lane >> 2, qc = lane & 3;
    const uint32_t swl = lane & 7;               // swizzle key (row & 7)
    const float4 z4 = make_float4(0.f, 0.f, 0.f, 0.f);

    auto cpa_M = [&](uint32_t dstoff, int axis) {
        const __half* Mg = &g_Mhf[axis][0][0];
#pragma unroll
        for (int u = 0; u < 4; u++) {
            int s = tid + u * NTHR;   // 2048 x 16B chunks
            uint32_t r = (uint32_t)s >> 4, g = (uint32_t)s & 15;
            cpa16(sb + dstoff + r * 256 + ((g ^ (r & 7)) << 4),
                  Mg + r * 128 + g * 8);
        }
        cpa_commit();
    };

    // ---- X staging: 8192 float4 = 2 chunks of 8/thread, swizzled store ----
    auto x_ld8 = [&](int t, int g, float4* v) {
        int b = t >> 8, h0 = ((t >> 4) & 15) * 16, w0 = (t & 15) * 16;
        const float* xb = x + ((b * 256 + h0) * 256 + w0) * 128;
#pragma unroll
        for (int u = 0; u < 8; u++) {
            int s = tid + (g * 8 + u) * NTHR;
            int r = s >> 5, c4 = s & 31;
            v[u] = __ldg((const float4*)(xb + ((r >> 4) * 256 + (r & 15)) * 128 + c4 * 4));
        }
    };
    auto x_st8 = [&](int g, const float4* v) {
#pragma unroll
        for (int u = 0; u < 8; u++) {
            int s = tid + (g * 8 + u) * NTHR;
            uint32_t r = (uint32_t)s >> 5, c4 = (uint32_t)s & 31;
            uint32_t off = r * 256 + (((c4 >> 1) ^ (r & 7)) << 4) + (c4 & 1) * 8;
            *(ull*)(sm + OFF_X + off) = pack4h(v[u]);
        }
    };
    // ---- KV halo: 10368 float4 (324 rows x 272B, padded) ----
    auto kv_addr = [&](int t, int s) -> const float4* {
        int b = t >> 8, h0 = ((t >> 4) & 15) * 16, w0 = (t & 15) * 16;
        int kvi = s >> 5, c4 = s & 31;
        int a = kvi / 18, bw = kvi - a * 18;
        int gh = h0 - 1 + a, gw = w0 - 1 + bw;
        bool ok = (gh >= 0) && (gh < T) && (gw >= 0) && (gw < T);
        return ok ? (const float4*)(kv + ((b * 256 + gh) * 256 + gw) * 128 + c4 * 4)
                  : (const float4*)nullptr;
    };
    auto kv_ld8 = [&](int t, int g, float4* v) {
#pragma unroll
        for (int u = 0; u < 8; u++) {
            const float4* p = kv_addr(t, tid + (g * 8 + u) * NTHR);
            v[u] = p ? __ldg(p) : z4;
        }
    };
    auto kv_st8 = [&](int g, const float4* v) {
#pragma unroll
        for (int u = 0; u < 8; u++) {
            int s = tid + (g * 8 + u) * NTHR;
            *(ull*)(sm + OFF_KV + (uint32_t)(s >> 5) * 272 + (uint32_t)(s & 31) * 8) =
                pack4h(v[u]);
        }
    };
    auto kv_ld4 = [&](int t, float4* v) {
#pragma unroll
        for (int u = 0; u < 4; u++) {
            const float4* p = kv_addr(t, tid + (16 + u) * NTHR);
            v[u] = p ? __ldg(p) : z4;
        }
    };
    auto kv_st4 = [&](const float4* v) {
#pragma unroll
        for (int u = 0; u < 4; u++) {
            int s = tid + (16 + u) * NTHR;
            *(ull*)(sm + OFF_KV + (uint32_t)(s >> 5) * 272 + (uint32_t)(s & 31) * 8) =
                pack4h(v[u]);
        }
    };
    auto kv_rem_ld = [&](int t) -> float4 {
        if (tid >= 128) return z4;
        const float4* p = kv_addr(t, tid + 10240);
        return p ? __ldg(p) : z4;
    };
    auto kv_rem_st = [&](float4 v) {
        if (tid >= 128) return;
        int s = tid + 10240;
        *(ull*)(sm + OFF_KV + (uint32_t)(s >> 5) * 272 + (uint32_t)(s & 31) * 8) =
            pack4h(v);
    };

    // ---- ldmatrix row bases (swizzled layout) ----
    uint32_t arow[2], brow[4];
#pragma unroll
    for (int mi = 0; mi < 2; mi++)
        arow[mi] = (uint32_t)(32 * rg + 16 * mi + (lane & 15)) * 256;
#pragma unroll
    for (int ng = 0; ng < 4; ng++)
        brow[ng] = (uint32_t)(64 * cg + 16 * ng + ((lane >> 4) << 3) + (lane & 7)) * 256;
    const uint32_t xbase = sb + OFF_X;
    const uint32_t ga0 = (uint32_t)(lane >> 4);       // A 16B-group lsb
    const uint32_t gb0 = (uint32_t)((lane >> 3) & 1); // B 16B-group lsb

    float acc[2][8][4];

    auto run_gemm = [&](uint32_t mbase) {
#pragma unroll
        for (int mi = 0; mi < 2; mi++)
#pragma unroll
            for (int nt = 0; nt < 8; nt++)
#pragma unroll
                for (int u = 0; u < 4; u++) acc[mi][nt][u] = 0.f;
#pragma unroll 1
        for (int ks = 0; ks < 8; ks++) {
            const uint32_t ga = ((ga0 + 2 * (uint32_t)ks) ^ swl) << 4;
            const uint32_t gb = ((gb0 + 2 * (uint32_t)ks) ^ swl) << 4;
            uint32_t ah[2][4], bh[4][4];
#pragma unroll
            for (int mi = 0; mi < 2; mi++) ldsm4(ah[mi], xbase + arow[mi] + ga);
#pragma unroll
            for (int ng = 0; ng < 4; ng++) ldsm4(bh[ng], mbase + brow[ng] + gb);
#pragma unroll
            for (int mi = 0; mi < 2; mi++)
#pragma unroll
                for (int ng = 0; ng < 4; ng++) {
                    mmah(acc[mi][2 * ng],     ah[mi], bh[ng][0], bh[ng][1]);
                    mmah(acc[mi][2 * ng + 1], ah[mi], bh[ng][2], bh[ng][3]);
                }
        }
    };

    // repack acc -> fp16 A fragments (acc layout == A-frag layout); frees acc
    auto repack = [&](uint32_t af[2][4][4]) {
#pragma unroll
        for (int mi = 0; mi < 2; mi++)
#pragma unroll
            for (int kl = 0; kl < 4; kl++) {
                af[mi][kl][0] = packh2(acc[mi][2 * kl][0],     acc[mi][2 * kl][1]);
                af[mi][kl][1] = packh2(acc[mi][2 * kl][2],     acc[mi][2 * kl][3]);
                af[mi][kl][2] = packh2(acc[mi][2 * kl + 1][0], acc[mi][2 * kl + 1][1]);
                af[mi][kl][3] = packh2(acc[mi][2 * kl + 1][2], acc[mi][2 * kl + 1][3]);
            }
    };

    // B-frag load: kv halo row `row`, channel-h2 index (32cg + 8kl + qc) (+4 for b1)
    auto bload = [&](uint32_t row, int kl, uint32_t& b0, uint32_t& b1) {
        const char* p = sm + OFF_KV + row * 272 + ((uint32_t)(32 * cg + 8 * kl + qc)) * 4;
        b0 = *(const uint32_t*)p;
        b1 = *(const uint32_t*)(p + 16);
    };
    auto dots_w = [&](const uint32_t af[2][4][4]) {
        float* PT = (float*)(sm + OFF_PTW);
#pragma unroll
        for (int mi = 0; mi < 2; mi++) {
            const int rb = 2 * rg + mi;
#pragma unroll
            for (int jt = 0; jt < 3; jt++) {
                float dv[4] = {0.f, 0.f, 0.f, 0.f};
                uint32_t b0[4], b1[4];
#pragma unroll
                for (int kl = 0; kl < 4; kl++)
                    bload((uint32_t)((rb + 1) * 18 + 8 * jt + qrow), kl, b0[kl], b1[kl]);
#pragma unroll
                for (int kl = 0; kl < 4; kl++) mmah(dv, af[mi][kl], b0[kl], b1[kl]);
#pragma unroll
                for (int u = 0; u < 2; u++) {
                    int j = 8 * jt + 2 * qc + u;
                    int dd0 = j - qrow;
                    if (dd0 >= 0 && dd0 < 3)
                        PT[(dd0 * 256 + 16 * rb + qrow) * 2 + cg] = dv[u];
                    int dd1 = j - (qrow + 8);
                    if (dd1 >= 0 && dd1 < 3)
                        PT[(dd1 * 256 + 16 * rb + qrow + 8) * 2 + cg] = dv[2 + u];
                }
            }
        }
    };
    auto dots_h = [&](const uint32_t af[2][4][4]) {
        float* PT = (float*)(sm + OFF_PTH);
#pragma unroll
        for (int mi = 0; mi < 2; mi++) {
            const int rb = 2 * rg + mi;
#pragma unroll
            for (int dd = 0; dd < 3; dd++)
#pragma unroll
                for (int jt = 0; jt < 2; jt++) {
                    float dv[4] = {0.f, 0.f, 0.f, 0.f};
                    uint32_t b0[4], b1[4];
#pragma unroll
                    for (int kl = 0; kl < 4; kl++)
                        bload((uint32_t)((rb + dd) * 18 + 8 * jt + qrow + 1), kl,
                              b0[kl], b1[kl]);
#pragma unroll
                    for (int kl = 0; kl < 4; kl++) mmah(dv, af[mi][kl], b0[kl], b1[kl]);
#pragma unroll
                    for (int u = 0; u < 2; u++) {
                        int j = 8 * jt + 2 * qc + u;
                        if (j == qrow)
                            PT[(dd * 256 + 16 * rb + qrow) * 2 + cg] = dv[u];
                        if (j == qrow + 8)
                            PT[(dd * 256 + 16 * rb + qrow + 8) * 2 + cg] = dv[2 + u];
                    }
                }
        }
    };

    // inline 3-way band softmax from a PT buffer (per-thread, redundant x2)
    auto band_w = [&](uint32_t ptoff, int pos, int gp, float* w) {
        const float* PT = (const float*)(sm + ptoff);
        float d0 = PT[(0 * 256 + pos) * 2] + PT[(0 * 256 + pos) * 2 + 1];
        float d1 = PT[(1 * 256 + pos) * 2] + PT[(1 * 256 + pos) * 2 + 1];
        float d2 = PT[(2 * 256 + pos) * 2] + PT[(2 * 256 + pos) * 2 + 1];
        float m = d1;
        if (gp > 0)     m = fmaxf(m, d0);
        if (gp < T - 1) m = fmaxf(m, d2);
        float w0e = (gp > 0)     ? __expf(d0 - m) : 0.f;
        float w1e = __expf(d1 - m);
        float w2e = (gp < T - 1) ? __expf(d2 - m) : 0.f;
        float inv = 1.f / (w0e + w1e + w2e);
        w[0] = w0e * inv; w[1] = w1e * inv; w[2] = w2e * inv;
    };

    auto combine = [&](int t) {
        int b = t >> 8, h0 = ((t >> 4) & 15) * 16, w0 = (t & 15) * 16;
        int p  = tid >> 1;
        int hf = tid & 1;
        int hh = p >> 4, wv = p & 15;
        int kvc = (hh + 1) * 18 + wv + 1;
        float ww[3], wh[3];
        band_w(OFF_PTW, p, w0 + wv, ww);
        band_w(OFF_PTH, p, h0 + hh, wh);
        float wc = ww[1] + wh[1];
        float4* go = (float4*)(out + ((b * 256 + h0 + hh) * 256 + (w0 + wv)) * 128);
#pragma unroll
        for (int u = 0; u < 16; u++) {
            int c4 = 2 * u + hf;          // pair-adjacent: conflict-free
            uint2 aL = *(const uint2*)(sm + OFF_KV + (kvc - 1)  * 272 + c4 * 8);
            uint2 aC = *(const uint2*)(sm + OFF_KV + kvc        * 272 + c4 * 8);
            uint2 aR = *(const uint2*)(sm + OFF_KV + (kvc + 1)  * 272 + c4 * 8);
            uint2 aU = *(const uint2*)(sm + OFF_KV + (kvc - 18) * 272 + c4 * 8);
            uint2 aD = *(const uint2*)(sm + OFF_KV + (kvc + 18) * 272 + c4 * 8);
            float2 l0 = __half22float2(*(__half2*)&aL.x), l1 = __half22float2(*(__half2*)&aL.y);
            float2 c0 = __half22float2(*(__half2*)&aC.x), c1 = __half22float2(*(__half2*)&aC.y);
            float2 r0 = __half22float2(*(__half2*)&aR.x), r1 = __half22float2(*(__half2*)&aR.y);
            float2 u0 = __half22float2(*(__half2*)&aU.x), u1 = __half22float2(*(__half2*)&aU.y);
            float2 d0 = __half22float2(*(__half2*)&aD.x), d1 = __half22float2(*(__half2*)&aD.y);
            float4 r;
            r.x = ww[0] * l0.x + wc * c0.x + ww[2] * r0.x + wh[0] * u0.x + wh[2] * d0.x;
            r.y = ww[0] * l0.y + wc * c0.y + ww[2] * r0.y + wh[0] * u0.y + wh[2] * d0.y;
            r.z = ww[0] * l1.x + wc * c1.x + ww[2] * r1.x + wh[0] * u1.x + wh[2] * d1.x;
            r.w = ww[0] * l1.y + wc * c1.y + ww[2] * r1.y + wh[0] * u1.y + wh[2] * d1.y;
            go[c4] = r;
        }
    };

    // ---- prologue: both M (once), X(t0), KV(t0) ----
    const int t0 = blockIdx.x, stride = gridDim.x;
    if (t0 < NTILES) {
        cpa_M(OFF_MW, 0);
        cpa_M(OFF_MH2, 1);
        float4 v[8];
#pragma unroll 1
        for (int g = 0; g < 2; g++) { x_ld8(t0, g, v); x_st8(g, v); }
#pragma unroll 1
        for (int g = 0; g < 2; g++) { kv_ld8(t0, g, v); kv_st8(g, v); }
        kv_ld4(t0, v); kv_st4(v);
        kv_rem_st(kv_rem_ld(t0));
        cpa_wait0();
    }
    __syncthreads();

    for (int t = t0; t < NTILES; t += stride) {
        const int tn = t + stride;
        const bool hn = tn < NTILES;

        // ---- compute chain: acc freed early via repack ----
        uint32_t af_w[2][4][4], af_h[2][4][4];
        run_gemm(sb + OFF_MW);
        repack(af_w);
        run_gemm(sb + OFF_MH2);
        repack(af_h);
        float4 xsA[8];
        if (hn) x_ld8(tn, 0, xsA);                // LDG under dots
        dots_w(af_w);
        dots_h(af_h);
        __syncthreads();                          // bar A: PT ready, X reads done

        // ---- stage X(tn); deep KV prefetch (acc/af dead); combine ----
        float4 kva[8], kvb[8];
        if (hn) {
            x_st8(0, xsA);
            x_ld8(tn, 1, xsA);
            kv_ld8(tn, 0, kva);                   // issue burst covers xsA latency
            x_st8(1, xsA);
            kv_ld8(tn, 1, kvb);
        }
        combine(t);
        __syncthreads();                          // bar B: KV reads done

        // ---- KV(tn) restage (all data already in registers) ----
        if (hn) {
            kv_st8(0, kva);
            kv_st8(1, kvb);
            float4 kc4[4];
            kv_ld4(tn, kc4);
            float4 rr = kv_rem_ld(tn);
            kv_st4(kc4);
            kv_rem_st(rr);
        }
        __syncthreads();                          // bar C: staged for tn
    }
}

// ---------------------------------------------------------------------------
extern "C" void kernel_launch(void* const* d_in, const int* in_sizes, int n_in,
                              void* d_out, int out_size) {
    const float* x    = (const float*)d_in[0];
    const float* kv   = (const float*)d_in[1];
    const float* Wq_h = (const float*)d_in[2];
    const float* Wk_h = (const float*)d_in[3];
    const float* Wq_w = (const float*)d_in[4];
    const float* Wk_w = (const float*)d_in[5];
    float* out = (float*)d_out;

    cudaFuncSetAttribute(axial_fused,
                         cudaFuncAttributeMaxDynamicSharedMemorySize, SMEM_TOTAL);

    int nsm = 148;
    cudaDeviceGetAttribute(&nsm, cudaDevAttrMultiProcessorCount, 0);
    if (nsm <= 0) nsm = 148;
    int grid = nsm < NTILES ? nsm : NTILES;

    compute_M_kernel<<<dim3(128, 2), 128>>>(Wq_h, Wk_h, Wq_w, Wk_w);
    axial_fused<<<grid, NTHR, SMEM_TOTAL>>>(x, kv, out);
}

// round 17
// speedup vs baseline: 1.2184x; 1.2184x over previous
#include <cuda_runtime.h>
#include <cuda_fp16.h>
#include <cstdint>

#define D 128
#define T 256
#define NTILES 1024          // 4 batches * 16 * 16 spatial tiles
#define NTHR 512
#define SCALE 0.08838834764831845f   // 128^-0.5

typedef unsigned long long ull;

// Packed fp16 M^T per axis: g_Mhf[axis][j][k] = (Wq^T Wk)[k,j] * SCALE
__device__ __half g_Mhf[2][D][D];

// ---- smem byte layout ----
// M/X: XOR-swizzled 256B rows (16B group g at row r lives at g^(r&7))
#define OFF_MW 0                 // fp16 M_w [128][128h] swizzled   32768 B
#define OFF_MH2 32768            // fp16 M_h [128][128h] swizzled   32768 B
#define OFF_X  65536             // fp16 X   [256][128h] swizzled   65536 B
#define OFF_KV 131072            // fp16 KV  [324 rows][136h pad]   88128 B
#define OFF_PTW 219200           // fp32 W partials [3][256][2]      6144 B
#define OFF_PTH 225344           // fp32 H partials [3][256][2]      6144 B
#define SMEM_TOTAL 231488

// ---------------------------------------------------------------------------
__device__ __forceinline__ uint32_t smem_u32(const void* p) {
    uint32_t a;
    asm("{ .reg .u64 t; cvta.to.shared.u64 t, %1; cvt.u32.u64 %0, t; }"
        : "=r"(a) : "l"(p));
    return a;
}
__device__ __forceinline__ void cpa16(uint32_t dst, const void* src) {
    asm volatile("cp.async.cg.shared.global [%0], [%1], 16;"
                 :: "r"(dst), "l"(src));
}
__device__ __forceinline__ void cpa_commit() {
    asm volatile("cp.async.commit_group;");
}
__device__ __forceinline__ void cpa_wait0() {
    asm volatile("cp.async.wait_group 0;" ::: "memory");
}
__device__ __forceinline__ void ldsm4(uint32_t* r, uint32_t a) {
    asm volatile("ldmatrix.sync.aligned.m8n8.x4.shared.b16 {%0,%1,%2,%3}, [%4];"
                 : "=r"(r[0]), "=r"(r[1]), "=r"(r[2]), "=r"(r[3]) : "r"(a));
}
__device__ __forceinline__ void mmah(float* d, const uint32_t* a,
                                     uint32_t b0, uint32_t b1) {
    asm volatile(
        "mma.sync.aligned.m16n8k16.row.col.f32.f16.f16.f32 "
        "{%0,%1,%2,%3},{%4,%5,%6,%7},{%8,%9},{%0,%1,%2,%3};"
        : "+f"(d[0]), "+f"(d[1]), "+f"(d[2]), "+f"(d[3])
        : "r"(a[0]), "r"(a[1]), "r"(a[2]), "r"(a[3]), "r"(b0), "r"(b1));
}
__device__ __forceinline__ ull pack4h(float4 v) {
    __half2 h0 = __floats2half2_rn(v.x, v.y);
    __half2 h1 = __floats2half2_rn(v.z, v.w);
    unsigned u0 = *(unsigned*)&h0, u1 = *(unsigned*)&h1;
    return (ull)u0 | ((ull)u1 << 32);
}

// ---------------------------------------------------------------------------
// Kernel 1 (v2): M^T[j][k] = sum_e Wq[e,k] * Wk[e,j] * SCALE -> fp16
// grid (8, 2): 16 k-columns per block; smem-staged operands, coalesced.
// FMA order identical to v1 (ascending e) -> bit-identical M.
// ---------------------------------------------------------------------------
__global__ void compute_M_kernel(const float* __restrict__ Wq_h,
                                 const float* __restrict__ Wk_h,
                                 const float* __restrict__ Wq_w,
                                 const float* __restrict__ Wk_w) {
    extern __shared__ float cms[];
    float* wk_s = cms;              // [128][128]
    float* wq_s = cms + D * D;      // [128][16]
    const int tid = threadIdx.x;
    const int axis = blockIdx.y;
    const int k0 = blockIdx.x * 16;
    const float* Wq = axis ? Wq_h : Wq_w;
    const float* Wk = axis ? Wk_h : Wk_w;

    // stage Wk [e][j] fully (4096 float4, coalesced)
#pragma unroll
    for (int i = 0; i < 8; i++) {
        int s = tid + i * 512;
        ((float4*)wk_s)[s] = ((const float4*)Wk)[s];
    }
    // stage Wq tile [e][k0..k0+15] (512 float4)
    {
        int e = tid >> 2, q = tid & 3;
        ((float4*)(wq_s + e * 16))[q] =
            *(const float4*)(Wq + e * D + k0 + 4 * q);
    }
    __syncthreads();

    const int j = tid & 127;
    const int kk0 = tid >> 7;       // 0..3
    float s0 = 0.f, s1 = 0.f, s2 = 0.f, s3 = 0.f;
#pragma unroll 8
    for (int e = 0; e < D; e++) {
        float wv = wk_s[e * D + j];
        const float* wq = wq_s + e * 16 + kk0;
        s0 = fmaf(wq[0],  wv, s0);
        s1 = fmaf(wq[4],  wv, s1);
        s2 = fmaf(wq[8],  wv, s2);
        s3 = fmaf(wq[12], wv, s3);
    }
    __half* Mo = &g_Mhf[axis][j][k0 + kk0];
    Mo[0]  = __float2half(s0 * SCALE);
    Mo[4]  = __float2half(s1 * SCALE);
    Mo[8]  = __float2half(s2 * SCALE);
    Mo[12] = __float2half(s3 * SCALE);
}

// ---------------------------------------------------------------------------
// Kernel 2: persistent fused both-axis axial attention, 16x16 tiles,
// 512 threads, both M resident, 3 barriers/tile, inline softmax at combine.
// (R14 structure: known-good at 128-reg budget.)
// ---------------------------------------------------------------------------
__global__ __launch_bounds__(NTHR, 1)
void axial_fused(const float* __restrict__ x, const float* __restrict__ kv,
                 float* __restrict__ out) {
    extern __shared__ char sm[];
    const uint32_t sb = smem_u32(sm);
    const int tid = threadIdx.x, wid = tid >> 5, lane = tid & 31;
    const int rg = wid >> 1, cg = wid & 1;       // 8 row-groups x 2 col-groups
    const int qrow = lane >> 2, qc = lane & 3;
    const uint32_t swl = lane & 7;               // swizzle key (row & 7)
    const float4 z4 = make_float4(0.f, 0.f, 0.f, 0.f);

    auto cpa_M = [&](uint32_t dstoff, int axis) {
        const __half* Mg = &g_Mhf[axis][0][0];
#pragma unroll
        for (int u = 0; u < 4; u++) {
            int s = tid + u * NTHR;   // 2048 x 16B chunks
            uint32_t r = (uint32_t)s >> 4, g = (uint32_t)s & 15;
            cpa16(sb + dstoff + r * 256 + ((g ^ (r & 7)) << 4),
                  Mg + r * 128 + g * 8);
        }
        cpa_commit();
    };

    // ---- X staging: 8192 float4 = 2 chunks of 8/thread, swizzled store ----
    auto x_ld8 = [&](int t, int g, float4* v) {
        int b = t >> 8, h0 = ((t >> 4) & 15) * 16, w0 = (t & 15) * 16;
        const float* xb = x + ((b * 256 + h0) * 256 + w0) * 128;
#pragma unroll
        for (int u = 0; u < 8; u++) {
            int s = tid + (g * 8 + u) * NTHR;
            int r = s >> 5, c4 = s & 31;
            v[u] = __ldg((const float4*)(xb + ((r >> 4) * 256 + (r & 15)) * 128 + c4 * 4));
        }
    };
    auto x_st8 = [&](int g, const float4* v) {
#pragma unroll
        for (int u = 0; u < 8; u++) {
            int s = tid + (g * 8 + u) * NTHR;
            uint32_t r = (uint32_t)s >> 5, c4 = (uint32_t)s & 31;
            uint32_t off = r * 256 + (((c4 >> 1) ^ (r & 7)) << 4) + (c4 & 1) * 8;
            *(ull*)(sm + OFF_X + off) = pack4h(v[u]);
        }
    };
    // ---- KV halo: 10368 float4 (324 rows x 272B, padded) ----
    auto kv_addr = [&](int t, int s) -> const float4* {
        int b = t >> 8, h0 = ((t >> 4) & 15) * 16, w0 = (t & 15) * 16;
        int kvi = s >> 5, c4 = s & 31;
        int a = kvi / 18, bw = kvi - a * 18;
        int gh = h0 - 1 + a, gw = w0 - 1 + bw;
        bool ok = (gh >= 0) && (gh < T) && (gw >= 0) && (gw < T);
        return ok ? (const float4*)(kv + ((b * 256 + gh) * 256 + gw) * 128 + c4 * 4)
                  : (const float4*)nullptr;
    };
    auto kv_ld8 = [&](int t, int g, float4* v) {
#pragma unroll
        for (int u = 0; u < 8; u++) {
            const float4* p = kv_addr(t, tid + (g * 8 + u) * NTHR);
            v[u] = p ? __ldg(p) : z4;
        }
    };
    auto kv_st8 = [&](int g, const float4* v) {
#pragma unroll
        for (int u = 0; u < 8; u++) {
            int s = tid + (g * 8 + u) * NTHR;
            *(ull*)(sm + OFF_KV + (uint32_t)(s >> 5) * 272 + (uint32_t)(s & 31) * 8) =
                pack4h(v[u]);
        }
    };
    auto kv_ld4 = [&](int t, float4* v) {
#pragma unroll
        for (int u = 0; u < 4; u++) {
            const float4* p = kv_addr(t, tid + (16 + u) * NTHR);
            v[u] = p ? __ldg(p) : z4;
        }
    };
    auto kv_st4 = [&](const float4* v) {
#pragma unroll
        for (int u = 0; u < 4; u++) {
            int s = tid + (16 + u) * NTHR;
            *(ull*)(sm + OFF_KV + (uint32_t)(s >> 5) * 272 + (uint32_t)(s & 31) * 8) =
                pack4h(v[u]);
        }
    };
    auto kv_rem_ld = [&](int t) -> float4 {
        if (tid >= 128) return z4;
        const float4* p = kv_addr(t, tid + 10240);
        return p ? __ldg(p) : z4;
    };
    auto kv_rem_st = [&](float4 v) {
        if (tid >= 128) return;
        int s = tid + 10240;
        *(ull*)(sm + OFF_KV + (uint32_t)(s >> 5) * 272 + (uint32_t)(s & 31) * 8) =
            pack4h(v);
    };

    // ---- ldmatrix row bases (swizzled layout) ----
    uint32_t arow[2], brow[4];
#pragma unroll
    for (int mi = 0; mi < 2; mi++)
        arow[mi] = (uint32_t)(32 * rg + 16 * mi + (lane & 15)) * 256;
#pragma unroll
    for (int ng = 0; ng < 4; ng++)
        brow[ng] = (uint32_t)(64 * cg + 16 * ng + ((lane >> 4) << 3) + (lane & 7)) * 256;
    const uint32_t xbase = sb + OFF_X;
    const uint32_t ga0 = (uint32_t)(lane >> 4);       // A 16B-group lsb
    const uint32_t gb0 = (uint32_t)((lane >> 3) & 1); // B 16B-group lsb

    float acc[2][8][4];

    auto run_gemm = [&](uint32_t mbase) {
#pragma unroll
        for (int mi = 0; mi < 2; mi++)
#pragma unroll
            for (int nt = 0; nt < 8; nt++)
#pragma unroll
                for (int u = 0; u < 4; u++) acc[mi][nt][u] = 0.f;
#pragma unroll 1
        for (int ks = 0; ks < 8; ks++) {
            const uint32_t ga = ((ga0 + 2 * (uint32_t)ks) ^ swl) << 4;
            const uint32_t gb = ((gb0 + 2 * (uint32_t)ks) ^ swl) << 4;
            uint32_t ah[2][4], bh[4][4];
#pragma unroll
            for (int mi = 0; mi < 2; mi++) ldsm4(ah[mi], xbase + arow[mi] + ga);
#pragma unroll
            for (int ng = 0; ng < 4; ng++) ldsm4(bh[ng], mbase + brow[ng] + gb);
#pragma unroll
            for (int mi = 0; mi < 2; mi++)
#pragma unroll
                for (int ng = 0; ng < 4; ng++) {
                    mmah(acc[mi][2 * ng],     ah[mi], bh[ng][0], bh[ng][1]);
                    mmah(acc[mi][2 * ng + 1], ah[mi], bh[ng][2], bh[ng][3]);
                }
        }
    };

    auto run_dots = [&](int kstep, uint32_t ptoff) {
        const __half2* KH = (const __half2*)(sm + OFF_KV);
        float prt[12];
#pragma unroll
        for (int mi = 0; mi < 2; mi++)
#pragma unroll
            for (int h = 0; h < 2; h++) {
                int r = 32 * rg + 16 * mi + 8 * h + qrow;
                int kvc = ((r >> 4) + 1) * 18 + (r & 15) + 1;
#pragma unroll
                for (int dd = 0; dd < 3; dd++) {
                    int kvrow = kvc + (dd - 1) * kstep;
                    float s = 0.f;
#pragma unroll
                    for (int nt = 0; nt < 8; nt++) {
                        float2 kp = __half22float2(
                            KH[kvrow * 68 + 32 * cg + 4 * nt + qc]);
                        s = fmaf(acc[mi][nt][2 * h],     kp.x, s);
                        s = fmaf(acc[mi][nt][2 * h + 1], kp.y, s);
                    }
                    prt[(mi * 2 + h) * 3 + dd] = s;
                }
            }
#pragma unroll
        for (int i = 0; i < 12; i++) {
            float v = prt[i];
            v += __shfl_xor_sync(0xffffffffu, v, 1);
            v += __shfl_xor_sync(0xffffffffu, v, 2);
            prt[i] = v;
        }
        if (qc == 0) {
            float* PT = (float*)(sm + ptoff);
#pragma unroll
            for (int mi = 0; mi < 2; mi++)
#pragma unroll
                for (int h = 0; h < 2; h++) {
                    int r = 32 * rg + 16 * mi + 8 * h + qrow;
#pragma unroll
                    for (int dd = 0; dd < 3; dd++)
                        PT[(dd * 256 + r) * 2 + cg] = prt[(mi * 2 + h) * 3 + dd];
                }
        }
    };

    // inline 3-way band softmax from a PT buffer (per-thread, redundant x2)
    auto band_w = [&](uint32_t ptoff, int pos, int gp, float* w) {
        const float* PT = (const float*)(sm + ptoff);
        float d0 = PT[(0 * 256 + pos) * 2] + PT[(0 * 256 + pos) * 2 + 1];
        float d1 = PT[(1 * 256 + pos) * 2] + PT[(1 * 256 + pos) * 2 + 1];
        float d2 = PT[(2 * 256 + pos) * 2] + PT[(2 * 256 + pos) * 2 + 1];
        float m = d1;
        if (gp > 0)     m = fmaxf(m, d0);
        if (gp < T - 1) m = fmaxf(m, d2);
        float w0e = (gp > 0)     ? __expf(d0 - m) : 0.f;
        float w1e = __expf(d1 - m);
        float w2e = (gp < T - 1) ? __expf(d2 - m) : 0.f;
        float inv = 1.f / (w0e + w1e + w2e);
        w[0] = w0e * inv; w[1] = w1e * inv; w[2] = w2e * inv;
    };

    auto combine = [&](int t) {
        int b = t >> 8, h0 = ((t >> 4) & 15) * 16, w0 = (t & 15) * 16;
        int p  = tid >> 1;
        int hf = tid & 1;
        int hh = p >> 4, wv = p & 15;
        int kvc = (hh + 1) * 18 + wv + 1;
        float ww[3], wh[3];
        band_w(OFF_PTW, p, w0 + wv, ww);
        band_w(OFF_PTH, p, h0 + hh, wh);
        float wc = ww[1] + wh[1];
        float4* go = (float4*)(out + ((b * 256 + h0 + hh) * 256 + (w0 + wv)) * 128);
#pragma unroll
        for (int u = 0; u < 16; u++) {
            int c4 = 2 * u + hf;          // pair-adjacent: conflict-free
            uint2 aL = *(const uint2*)(sm + OFF_KV + (kvc - 1)  * 272 + c4 * 8);
            uint2 aC = *(const uint2*)(sm + OFF_KV + kvc        * 272 + c4 * 8);
            uint2 aR = *(const uint2*)(sm + OFF_KV + (kvc + 1)  * 272 + c4 * 8);
            uint2 aU = *(const uint2*)(sm + OFF_KV + (kvc - 18) * 272 + c4 * 8);
            uint2 aD = *(const uint2*)(sm + OFF_KV + (kvc + 18) * 272 + c4 * 8);
            float2 l0 = __half22float2(*(__half2*)&aL.x), l1 = __half22float2(*(__half2*)&aL.y);
            float2 c0 = __half22float2(*(__half2*)&aC.x), c1 = __half22float2(*(__half2*)&aC.y);
            float2 r0 = __half22float2(*(__half2*)&aR.x), r1 = __half22float2(*(__half2*)&aR.y);
            float2 u0 = __half22float2(*(__half2*)&aU.x), u1 = __half22float2(*(__half2*)&aU.y);
            float2 d0 = __half22float2(*(__half2*)&aD.x), d1 = __half22float2(*(__half2*)&aD.y);
            float4 r;
            r.x = ww[0] * l0.x + wc * c0.x + ww[2] * r0.x + wh[0] * u0.x + wh[2] * d0.x;
            r.y = ww[0] * l0.y + wc * c0.y + ww[2] * r0.y + wh[0] * u0.y + wh[2] * d0.y;
            r.z = ww[0] * l1.x + wc * c1.x + ww[2] * r1.x + wh[0] * u1.x + wh[2] * d1.x;
            r.w = ww[0] * l1.y + wc * c1.y + ww[2] * r1.y + wh[0] * u1.y + wh[2] * d1.y;
            go[c4] = r;
        }
    };

    // ---- prologue: both M (once), X(t0), KV(t0) ----
    const int t0 = blockIdx.x, stride = gridDim.x;
    if (t0 < NTILES) {
        cpa_M(OFF_MW, 0);
        cpa_M(OFF_MH2, 1);
        float4 v[8];
#pragma unroll 1
        for (int g = 0; g < 2; g++) { x_ld8(t0, g, v); x_st8(g, v); }
#pragma unroll 1
        for (int g = 0; g < 2; g++) { kv_ld8(t0, g, v); kv_st8(g, v); }
        kv_ld4(t0, v); kv_st4(v);
        kv_rem_st(kv_rem_ld(t0));
        cpa_wait0();
    }
    __syncthreads();

    for (int t = t0; t < NTILES; t += stride) {
        const int tn = t + stride;
        const bool hn = tn < NTILES;

        // ---- compute chain: no intra-chain barriers ----
        run_gemm(sb + OFF_MW);
        run_dots(1, OFF_PTW);
        run_gemm(sb + OFF_MH2);
        float4 xsA[8];
        if (hn) x_ld8(tn, 0, xsA);                // LDG under dots_h
        run_dots(18, OFF_PTH);
        __syncthreads();                          // bar A: PT ready, X reads done

        // ---- stage X(tn) + combine (inline softmax) ----
        if (hn) { x_st8(0, xsA); x_ld8(tn, 1, xsA); }
        float4 kva[8];
        if (hn) kv_ld8(tn, 0, kva);               // LDG under combine
        combine(t);
        if (hn) x_st8(1, xsA);
        __syncthreads();                          // bar B: KV reads done

        // ---- KV(tn) restage (ld4/rem latency hidden under chunk-1 wait) ----
        if (hn) {
            kv_st8(0, kva);
            kv_ld8(tn, 1, kva);
            float4 kc4[4];
            kv_ld4(tn, kc4);
            float4 rr = kv_rem_ld(tn);
            kv_st8(1, kva);
            kv_st4(kc4);
            kv_rem_st(rr);
        }
        __syncthreads();                          // bar C: staged for tn
    }
}

// ---------------------------------------------------------------------------
extern "C" void kernel_launch(void* const* d_in, const int* in_sizes, int n_in,
                              void* d_out, int out_size) {
    const float* x    = (const float*)d_in[0];
    const float* kv   = (const float*)d_in[1];
    const float* Wq_h = (const float*)d_in[2];
    const float* Wk_h = (const float*)d_in[3];
    const float* Wq_w = (const float*)d_in[4];
    const float* Wk_w = (const float*)d_in[5];
    float* out = (float*)d_out;

    constexpr int CM_SMEM = (D * D + D * 16) * 4;   // 73728 B

    cudaFuncSetAttribute(axial_fused,
                         cudaFuncAttributeMaxDynamicSharedMemorySize, SMEM_TOTAL);
    cudaFuncSetAttribute(compute_M_kernel,
                         cudaFuncAttributeMaxDynamicSharedMemorySize, CM_SMEM);

    int nsm = 148;
    cudaDeviceGetAttribute(&nsm, cudaDevAttrMultiProcessorCount, 0);
    if (nsm <= 0) nsm = 148;
    int grid = nsm < NTILES ? nsm : NTILES;

    compute_M_kernel<<<dim3(8, 2), 512, CM_SMEM>>>(Wq_h, Wk_h, Wq_w, Wk_w);
    axial_fused<<<grid, NTHR, SMEM_TOTAL>>>(x, kv, out);
}